// round 9
// baseline (speedup 1.0000x reference)
#include <cuda_runtime.h>
#include <math.h>

#define NB 512   // batch
#define NF 512   // features
#define NS 255   // splits
#define NN 511   // nodes
#define NC 21    // candidates

#define QSCALE 268435456.0                 // 2^28
#define QINV   3.7252902984619140625e-09f  // 2^-28

// ---------------- scratch (no allocations allowed) ----------------
__device__ unsigned long long g_qsplitI[NS * NB]; // [s][b] fixed-point accum (re-zeroed by scan blocks 1..16)
__device__ float g_qnodeT[NN * NB];               // [n][b]
__device__ float g_ga    [NN * NC];
__device__ float g_anode [NN];

// PDL: wait until the preceding kernel's writes are visible
__device__ __forceinline__ void pdl_wait() {
    asm volatile("griddepcontrol.wait;" ::: "memory");
}

// ================= kernel 1: split-K GEMM, 4x8 micro-tile =================
// qsplitT[s][b] = sum_f W[f][s] * x[b][f]; grid (ksplit=8, bTile=8, sTile=4), 128 thr.
// 32 FFMA : 3 LDS.128 per f -> FFMA-bound (old 4x4 was LDS-co-bound).
// Deterministic: fixed-point int64 atomic accumulation (per-thread f-order unchanged).
__global__ __launch_bounds__(128, 4)
void gemm_kernel(const float* __restrict__ x, const float* __restrict__ W)
{
    __shared__ float As[64][68];   // [f][s]
    __shared__ float Bs[64][68];   // [f][b]

    int tid   = threadIdx.x;
    int k0    = blockIdx.x * 64;
    int bBase = blockIdx.y * 64;
    int sBase = blockIdx.z * 64;

    {
        int s = tid & 63, f0 = tid >> 6;   // f0 in 0..1
        int gs = sBase + s;
#pragma unroll
        for (int i = 0; i < 32; i++) {
            int f = f0 + i * 2;
            As[f][s] = (gs < NS) ? W[(k0 + f) * NS + gs] : 0.0f;
        }
        int fb = tid & 63, b0 = tid >> 6;
#pragma unroll
        for (int i = 0; i < 32; i++) {
            int b = b0 + i * 2;
            Bs[fb][b] = x[(bBase + b) * NF + k0 + fb];
        }
    }
    __syncthreads();

    int tr = tid >> 3;   // 0..15: s quad
    int tc = tid & 7;    // 0..7 : b octet
    float acc[4][8];
#pragma unroll
    for (int i = 0; i < 4; i++)
#pragma unroll
        for (int j = 0; j < 8; j++) acc[i][j] = 0.0f;

#pragma unroll
    for (int f = 0; f < 64; f++) {
        float4 a4  = *(const float4*)&As[f][tr * 4];
        float4 b4a = *(const float4*)&Bs[f][tc * 8];
        float4 b4b = *(const float4*)&Bs[f][tc * 8 + 4];
        float av[4] = {a4.x, a4.y, a4.z, a4.w};
        float bv[8] = {b4a.x, b4a.y, b4a.z, b4a.w, b4b.x, b4b.y, b4b.z, b4b.w};
#pragma unroll
        for (int i = 0; i < 4; i++)
#pragma unroll
            for (int j = 0; j < 8; j++) acc[i][j] += av[i] * bv[j];
    }

#pragma unroll
    for (int i = 0; i < 4; i++) {
        int s = sBase + tr * 4 + i;
        if (s < NS) {
#pragma unroll
            for (int j = 0; j < 8; j++) {
                int b = bBase + tc * 8 + j;
                long long q = __double2ll_rn((double)acc[i][j] * QSCALE);
                atomicAdd(&g_qsplitI[s * NB + b], (unsigned long long)q);
            }
        }
    }
}

// ================= kernel 2: q_node (ancestor walk) + g_a reduction =================
__global__ __launch_bounds__(256)
void ga_kernel(const float* __restrict__ bias)
{
    pdl_wait();   // g_qsplitI must be complete

    int n   = blockIdx.x;
    int tid = threadIdx.x;

    float accs[NC];
#pragma unroll
    for (int c = 0; c < NC; c++) accs[c] = 0.0f;

#pragma unroll
    for (int rep = 0; rep < 2; rep++) {
        int b = tid + rep * 256;
        float m = 1.0f;
        int a = n;
        while (a > 0) {
            int p = (a - 1) >> 1;
            float q = (float)(long long)g_qsplitI[p * NB + b] * QINV + bias[p];
            m = fminf(m, (a == 2 * p + 1) ? -q : q);
            a = p;
        }
        g_qnodeT[n * NB + b] = m;
        float qh = m + 0.5f;
#pragma unroll
        for (int c = 0; c < NC; c++) {
            float d = fminf((float)c * (1.0f / 20.0f) - qh, 0.0f);
            accs[c] = fmaf(d, d, accs[c]);
        }
    }

#pragma unroll
    for (int c = 0; c < NC; c++)
#pragma unroll
        for (int o = 16; o > 0; o >>= 1)
            accs[c] += __shfl_down_sync(0xffffffffu, accs[c], o);

    __shared__ float sW[8][NC];
    int w = tid >> 5, l = tid & 31;
    if (l == 0) {
#pragma unroll
        for (int c = 0; c < NC; c++) sW[w][c] = accs[c];
    }
    __syncthreads();
    if (tid < NC) {
        float s = 0.0f;
#pragma unroll
        for (int ww = 0; ww < 8; ww++) s += sW[ww][tid];
        float ac = (float)tid * (1.0f / 20.0f);
        g_ga[n * NC + tid] = 0.5f * ac * ac + 0.5f * s;
    }
}

// ================= kernel 3: scan (block 0) + accumulator re-zero (blocks 1..16) =====
__device__ __forceinline__ float softmin_serial(int g, const float* sGa, const int* sK)
{
    float kg = (float)sK[g];
    int c1 = 2 * g + 1, c2 = 2 * g + 2;
    float k1 = (c1 < NN) ? (float)sK[c1] : 0.0f;
    float k2 = (c2 < NN) ? (float)sK[c2] : 0.0f;
    const float* r0 = &sGa[g * NC];
    const float* r1 = (c1 < NN) ? &sGa[c1 * NC] : r0;
    const float* r2 = (c2 < NN) ? &sGa[c2 * NC] : r0;

    float v[NC];
    float m = -3.0e38f;
#pragma unroll
    for (int c = 0; c < NC; c++) {
        float t = (1.0f - kg) * r0[c] + k1 * r1[c] + k2 * r2[c];
        v[c] = -100.0f * t;
        m = fmaxf(m, v[c]);
    }
    float su = 0.0f, asu = 0.0f;
#pragma unroll
    for (int c = 0; c < NC; c++) {
        float e = __expf(v[c] - m);
        su += e;
        asu += (float)c * (1.0f / 20.0f) * e;
    }
    return asu / su;
}

// order-preserving float -> u32 (exact)
__device__ __forceinline__ unsigned fenc(float f)
{
    unsigned b = __float_as_uint(f);
    return (b & 0x80000000u) ? ~b : (b | 0x80000000u);
}

__global__ __launch_bounds__(256)
void scan_kernel()
{
    __shared__ float sGa[NN * NC];   // 42924 B (16B aligned: first shared object)
    __shared__ float sAgrp[NN];
    __shared__ float sAnode[NN];
    __shared__ int   sK[NN];

    pdl_wait();   // g_ga / last g_qsplitI readers must be complete

    int tid = threadIdx.x;

    if (blockIdx.x > 0) {
        // blocks 1..16: re-zero the GEMM fixed-point accumulator (hidden under block 0's scan)
        ulonglong2 z; z.x = 0ULL; z.y = 0ULL;
        ulonglong2* p = (ulonglong2*)g_qsplitI;
        for (int i = (int)(blockIdx.x - 1) * 256 + tid; i < NS * NB / 2; i += 16 * 256) p[i] = z;
        return;
    }

    // vectorized staging of g_ga (NN*NC = 10731 floats = 2682 float4 + 3)
    {
        const float4* d4 = (const float4*)g_ga;
        float4* s4 = (float4*)sGa;
        for (int i = tid; i < 2682; i += 256) s4[i] = d4[i];
        if (tid < 3) sGa[10728 + tid] = g_ga[10728 + tid];
    }
    for (int i = tid; i < NN; i += 256) sK[i] = 0;
    __syncthreads();

    // initial a_grp (k==0 -> own-row softmin); a_node == a_grp initially
    for (int i = tid; i < NN; i += 256) {
        const float* r = &sGa[i * NC];
        float m = -3.0e38f;
#pragma unroll
        for (int c = 0; c < NC; c++) m = fmaxf(m, -100.0f * r[c]);
        float su = 0.0f, asu = 0.0f;
#pragma unroll
        for (int c = 0; c < NC; c++) {
            float e = __expf(-100.0f * r[c] - m);
            su += e; asu += (float)c * (1.0f / 20.0f) * e;
        }
        float ag = asu / su;
        sAgrp[i]  = ag;
        sAnode[i] = ag;
    }
    __syncthreads();

    if (tid < 32) {
        int lane = tid;
        int applied = 0;
        const unsigned THRESH = fenc(1e-8f);
        for (;;) {
            // per-lane best over 16 interleaved nodes (conflict-free LDS, first-index ties)
            float bv = -3.0e38f; int bi = NN;
#pragma unroll
            for (int i = 0; i < 16; i++) {
                int n = i * 32 + lane;
                if (n < NN) {
                    float an = sAnode[n];
                    float ap = (n == 0) ? 1.0f : sAnode[(n - 1) >> 1];
                    float v = an - ap;
                    if (v > bv || (v == bv && n < bi)) { bv = v; bi = n; }
                }
            }
            // exact warp argmax via REDUX: max on encoded value, min index among max-lanes
            unsigned enc  = fenc(bv);
            unsigned vmax = __reduce_max_sync(0xffffffffu, enc);
            unsigned cand = (enc == vmax) ? (unsigned)bi : 0xffffffffu;
            unsigned gbi  = __reduce_min_sync(0xffffffffu, cand);
            int t = (vmax <= THRESH && gbi > 0u) ? (int)gbi : -1;   // all lanes agree

            if (t < 0 || applied >= NN) break;   // fixed point / 512th body's merge discarded
            applied++;
            if (lane == 0) sK[t] += 1;
            __syncwarp();

            int p = (t - 1) >> 1;
            // lanes 0 and 1 compute the two softmins in parallel, serially in registers
            float na = 0.0f;
            if (lane < 2) na = softmin_serial(lane == 0 ? p : t, sGa, sK);
            if (lane == 0) sAgrp[p] = na;
            else if (lane == 1) sAgrp[t] = na;
            __syncwarp();

            // incremental a_node refresh: exactly {p, t, sib(t), 2t+1, 2t+2}
            if (lane < 5) {
                int s0 = 2 * p + 1, s1 = 2 * p + 2;
                int sib = (s0 == t) ? s1 : s0;
                int m = (lane == 0) ? p : (lane == 1) ? t : (lane == 2) ? sib
                      : (lane == 3) ? 2 * t + 1 : 2 * t + 2;
                if (m < NN) {
                    float an;
                    if (m == 0) an = sAgrp[0];
                    else {
                        float k = (float)sK[m];
                        an = (1.0f - k) * sAgrp[m] + k * sAgrp[(m - 1) >> 1];
                    }
                    sAnode[m] = an;
                }
            }
            __syncwarp();
        }
    }
    __syncthreads();

    for (int i = tid; i < NN; i += 256) g_anode[i] = sAnode[i];
}

// ================= kernel 4: transposed trajectory (LDG.128 loads) =================
__global__ __launch_bounds__(256)
void traj_kernel(float* __restrict__ out)
{
    __shared__ float tile[32][33];

    pdl_wait();   // g_anode / g_qnodeT must be complete

    int tid = threadIdx.x;
    int tn = blockIdx.x >> 4, tb = blockIdx.x & 15;
    int n0 = tn * 32, b0 = tb * 32;

    // load: one float4 per thread, coalesced over b
    {
        int r = tid >> 3;        // 0..31
        int q = tid & 7;         // 0..7
        int n = n0 + r;
        float4 v4 = make_float4(0.0f, 0.0f, 0.0f, 0.0f);
        if (n < NN) {
            v4 = *(const float4*)&g_qnodeT[n * NB + b0 + q * 4];
            float a = g_anode[n];
            v4.x = fminf(fmaxf(v4.x, 0.0f), a);
            v4.y = fminf(fmaxf(v4.y, 0.0f), a);
            v4.z = fminf(fmaxf(v4.z, 0.0f), a);
            v4.w = fminf(fmaxf(v4.w, 0.0f), a);
        }
        int c = q * 4;
        tile[r][c + 0] = v4.x;
        tile[r][c + 1] = v4.y;
        tile[r][c + 2] = v4.z;
        tile[r][c + 3] = v4.w;
    }
    __syncthreads();

    // store: coalesced over n (out rows are 511 floats -> scalar stores)
#pragma unroll
    for (int pass = 0; pass < 4; pass++) {
        int r = (tid >> 5) + pass * 8, c = tid & 31;
        int n = n0 + c;
        if (n < NN) out[(b0 + r) * NN + n] = tile[c][r];
    }
}

// ---------------- launch (PDL on the three dependent kernels) ----------------
extern "C" void kernel_launch(void* const* d_in, const int* in_sizes, int n_in,
                              void* d_out, int out_size)
{
    const float* x = (const float*)d_in[0];
    const float* W = (const float*)d_in[1];
    const float* b = (const float*)d_in[2];
    // d_in[3] = max_depth (fixed at 8; shapes hardcoded)

    gemm_kernel<<<dim3(8, 8, 4), 128>>>(x, W);

    cudaLaunchAttribute attr[1];
    attr[0].id = cudaLaunchAttributeProgrammaticStreamSerialization;
    attr[0].val.programmaticStreamSerializationAllowed = 1;

    cudaLaunchConfig_t cfg = {};
    cfg.attrs = attr;
    cfg.numAttrs = 1;
    cfg.stream = 0;

    cfg.gridDim = dim3(NN); cfg.blockDim = dim3(256);
    cudaLaunchKernelEx(&cfg, ga_kernel, b);

    cfg.gridDim = dim3(17); cfg.blockDim = dim3(256);   // block 0 scan, 1..16 re-zero
    cudaLaunchKernelEx(&cfg, scan_kernel);

    cfg.gridDim = dim3(256); cfg.blockDim = dim3(256);
    cudaLaunchKernelEx(&cfg, traj_kernel, (float*)d_out);
}

// round 10
// speedup vs baseline: 1.0428x; 1.0428x over previous
#include <cuda_runtime.h>
#include <math.h>

#define NB 512   // batch
#define NF 512   // features
#define NS 255   // splits
#define NN 511   // nodes
#define NC 21    // candidates

#define QSCALE 268435456.0                 // 2^28
#define QINV   3.7252902984619140625e-09f  // 2^-28

// ---------------- scratch (no allocations allowed) ----------------
__device__ unsigned long long g_qsplitI[NS * NB]; // [s][b] fixed-point accum (re-zeroed by traj_kernel)
__device__ float g_qnode [NB * NN];               // [b][n]  (scatter-written by ga, coalesced-read by traj)
__device__ float g_ga    [NN * NC];
__device__ float g_anode [NN];

// PDL: wait until the preceding kernel's writes are visible
__device__ __forceinline__ void pdl_wait() {
    asm volatile("griddepcontrol.wait;" ::: "memory");
}

// ================= kernel 1: split-K GEMM, transposed output (FROZEN: R8) =================
// qsplitT[s][b] = sum_f W[f][s] * x[b][f]; grid (ksplit=8, bTile=8, sTile=4), 256 thr.
// Deterministic: fixed-point int64 atomic accumulation.
__global__ __launch_bounds__(256, 2)
void gemm_kernel(const float* __restrict__ x, const float* __restrict__ W)
{
    __shared__ float As[64][68];   // [f][s]
    __shared__ float Bs[64][68];   // [f][b]

    int tid   = threadIdx.x;
    int k0    = blockIdx.x * 64;
    int bBase = blockIdx.y * 64;
    int sBase = blockIdx.z * 64;

    {
        int s = tid & 63, f0 = tid >> 6;
#pragma unroll
        for (int i = 0; i < 16; i++) {
            int f = f0 + i * 4;
            int gs = sBase + s;
            As[f][s] = (gs < NS) ? W[(k0 + f) * NS + gs] : 0.0f;
        }
        int fb = tid & 63, b0 = tid >> 6;
#pragma unroll
        for (int i = 0; i < 16; i++) {
            int b = b0 + i * 4;
            Bs[fb][b] = x[(bBase + b) * NF + k0 + fb];
        }
    }
    __syncthreads();

    int tr = tid >> 4;   // s quad
    int tc = tid & 15;   // b quad
    float acc[4][4];
#pragma unroll
    for (int i = 0; i < 4; i++)
#pragma unroll
        for (int j = 0; j < 4; j++) acc[i][j] = 0.0f;

#pragma unroll
    for (int f = 0; f < 64; f++) {
        float4 a4 = *(const float4*)&As[f][tr * 4];
        float4 b4 = *(const float4*)&Bs[f][tc * 4];
        float av[4] = {a4.x, a4.y, a4.z, a4.w};
        float bv[4] = {b4.x, b4.y, b4.z, b4.w};
#pragma unroll
        for (int i = 0; i < 4; i++)
#pragma unroll
            for (int j = 0; j < 4; j++) acc[i][j] += av[i] * bv[j];
    }

#pragma unroll
    for (int i = 0; i < 4; i++) {
        int s = sBase + tr * 4 + i;
        if (s < NS) {
#pragma unroll
            for (int j = 0; j < 4; j++) {
                int b = bBase + tc * 4 + j;
                long long q = __double2ll_rn((double)acc[i][j] * QSCALE);
                atomicAdd(&g_qsplitI[s * NB + b], (unsigned long long)q);
            }
        }
    }
}

// ================= kernel 2: q_node (ancestor walk) + g_a; scatter-write [b][n] =================
__global__ __launch_bounds__(256)
void ga_kernel(const float* __restrict__ bias)
{
    pdl_wait();   // g_qsplitI must be complete

    int n   = blockIdx.x;
    int tid = threadIdx.x;

    float accs[NC];
#pragma unroll
    for (int c = 0; c < NC; c++) accs[c] = 0.0f;

#pragma unroll
    for (int rep = 0; rep < 2; rep++) {
        int b = tid + rep * 256;
        float m = 1.0f;
        int a = n;
        while (a > 0) {
            int p = (a - 1) >> 1;
            float q = (float)(long long)g_qsplitI[p * NB + b] * QINV + bias[p];
            m = fminf(m, (a == 2 * p + 1) ? -q : q);
            a = p;
        }
        g_qnode[b * NN + n] = m;        // scatter (fire-and-forget STG); traj reads coalesced
        float qh = m + 0.5f;
#pragma unroll
        for (int c = 0; c < NC; c++) {
            float d = fminf((float)c * (1.0f / 20.0f) - qh, 0.0f);
            accs[c] = fmaf(d, d, accs[c]);
        }
    }

#pragma unroll
    for (int c = 0; c < NC; c++)
#pragma unroll
        for (int o = 16; o > 0; o >>= 1)
            accs[c] += __shfl_down_sync(0xffffffffu, accs[c], o);

    __shared__ float sW[8][NC];
    int w = tid >> 5, l = tid & 31;
    if (l == 0) {
#pragma unroll
        for (int c = 0; c < NC; c++) sW[w][c] = accs[c];
    }
    __syncthreads();
    if (tid < NC) {
        float s = 0.0f;
#pragma unroll
        for (int ww = 0; ww < 8; ww++) s += sW[ww][tid];
        float ac = (float)tid * (1.0f / 20.0f);
        g_ga[n * NC + tid] = 0.5f * ac * ac + 0.5f * s;
    }
}

// ================= kernel 3: the scan (FROZEN: R8) =================
__device__ __forceinline__ float softmin_serial(int g, const float* sGa, const int* sK)
{
    float kg = (float)sK[g];
    int c1 = 2 * g + 1, c2 = 2 * g + 2;
    float k1 = (c1 < NN) ? (float)sK[c1] : 0.0f;
    float k2 = (c2 < NN) ? (float)sK[c2] : 0.0f;
    const float* r0 = &sGa[g * NC];
    const float* r1 = (c1 < NN) ? &sGa[c1 * NC] : r0;
    const float* r2 = (c2 < NN) ? &sGa[c2 * NC] : r0;

    float v[NC];
    float m = -3.0e38f;
#pragma unroll
    for (int c = 0; c < NC; c++) {
        float t = (1.0f - kg) * r0[c] + k1 * r1[c] + k2 * r2[c];
        v[c] = -100.0f * t;
        m = fmaxf(m, v[c]);
    }
    float su = 0.0f, asu = 0.0f;
#pragma unroll
    for (int c = 0; c < NC; c++) {
        float e = __expf(v[c] - m);
        su += e;
        asu += (float)c * (1.0f / 20.0f) * e;
    }
    return asu / su;
}

// order-preserving float -> u32 (exact)
__device__ __forceinline__ unsigned fenc(float f)
{
    unsigned b = __float_as_uint(f);
    return (b & 0x80000000u) ? ~b : (b | 0x80000000u);
}

__global__ __launch_bounds__(256)
void scan_kernel()
{
    __shared__ float sGa[NN * NC];   // 42924 B
    __shared__ float sAgrp[NN];
    __shared__ float sAnode[NN];
    __shared__ int   sK[NN];

    pdl_wait();   // g_ga must be complete

    int tid = threadIdx.x;

    for (int i = tid; i < NN * NC; i += 256) sGa[i] = g_ga[i];
    for (int i = tid; i < NN; i += 256) sK[i] = 0;
    __syncthreads();

    // initial a_grp (k==0 -> own-row softmin); a_node == a_grp initially
    for (int i = tid; i < NN; i += 256) {
        const float* r = &sGa[i * NC];
        float m = -3.0e38f;
#pragma unroll
        for (int c = 0; c < NC; c++) m = fmaxf(m, -100.0f * r[c]);
        float su = 0.0f, asu = 0.0f;
#pragma unroll
        for (int c = 0; c < NC; c++) {
            float e = __expf(-100.0f * r[c] - m);
            su += e; asu += (float)c * (1.0f / 20.0f) * e;
        }
        float ag = asu / su;
        sAgrp[i]  = ag;
        sAnode[i] = ag;
    }
    __syncthreads();

    if (tid < 32) {
        int lane = tid;
        int applied = 0;
        const unsigned THRESH = fenc(1e-8f);
        for (;;) {
            // per-lane best over 16 interleaved nodes (conflict-free LDS, first-index ties)
            float bv = -3.0e38f; int bi = NN;
#pragma unroll
            for (int i = 0; i < 16; i++) {
                int n = i * 32 + lane;
                if (n < NN) {
                    float an = sAnode[n];
                    float ap = (n == 0) ? 1.0f : sAnode[(n - 1) >> 1];
                    float v = an - ap;
                    if (v > bv || (v == bv && n < bi)) { bv = v; bi = n; }
                }
            }
            // exact warp argmax via REDUX: max on encoded value, min index among max-lanes
            unsigned enc  = fenc(bv);
            unsigned vmax = __reduce_max_sync(0xffffffffu, enc);
            unsigned cand = (enc == vmax) ? (unsigned)bi : 0xffffffffu;
            unsigned gbi  = __reduce_min_sync(0xffffffffu, cand);
            int t = (vmax <= THRESH && gbi > 0u) ? (int)gbi : -1;

            if (t < 0 || applied >= NN) break;   // fixed point / 512th body's merge discarded
            applied++;
            if (lane == 0) sK[t] += 1;
            __syncwarp();

            int p = (t - 1) >> 1;
            float na = 0.0f;
            if (lane < 2) na = softmin_serial(lane == 0 ? p : t, sGa, sK);
            if (lane == 0) sAgrp[p] = na;
            else if (lane == 1) sAgrp[t] = na;
            __syncwarp();

            // incremental a_node refresh: exactly {p, t, sib(t), 2t+1, 2t+2}
            if (lane < 5) {
                int s0 = 2 * p + 1, s1 = 2 * p + 2;
                int sib = (s0 == t) ? s1 : s0;
                int m = (lane == 0) ? p : (lane == 1) ? t : (lane == 2) ? sib
                      : (lane == 3) ? 2 * t + 1 : 2 * t + 2;
                if (m < NN) {
                    float an;
                    if (m == 0) an = sAgrp[0];
                    else {
                        float k = (float)sK[m];
                        an = (1.0f - k) * sAgrp[m] + k * sAgrp[(m - 1) >> 1];
                    }
                    sAnode[m] = an;
                }
            }
            __syncwarp();
        }
    }
    __syncthreads();

    for (int i = tid; i < NN; i += 256) g_anode[i] = sAnode[i];
}

// ================= kernel 4: elementwise clip (no transpose) + re-zero =================
// block b handles batch row b; fully coalesced both sides.
__global__ __launch_bounds__(512)
void traj_kernel(float* __restrict__ out)
{
    pdl_wait();   // g_anode / g_qnode must be complete

    int b   = blockIdx.x;
    int tid = threadIdx.x;
    if (tid < NN) {
        float q = g_qnode[b * NN + tid];
        out[b * NN + tid] = fminf(fmaxf(q, 0.0f), g_anode[tid]);
    }

    // re-zero fixed-point accumulator for next launch (512x512 threads cover 65280 elems)
    int i = b * 512 + tid;
    if (i < NS * NB / 2) {
        ulonglong2 z; z.x = 0ULL; z.y = 0ULL;
        ((ulonglong2*)g_qsplitI)[i] = z;
    }
}

// ---------------- launch (PDL on the three dependent kernels) ----------------
extern "C" void kernel_launch(void* const* d_in, const int* in_sizes, int n_in,
                              void* d_out, int out_size)
{
    const float* x = (const float*)d_in[0];
    const float* W = (const float*)d_in[1];
    const float* b = (const float*)d_in[2];
    // d_in[3] = max_depth (fixed at 8; shapes hardcoded)

    gemm_kernel<<<dim3(8, 8, 4), 256>>>(x, W);

    cudaLaunchAttribute attr[1];
    attr[0].id = cudaLaunchAttributeProgrammaticStreamSerialization;
    attr[0].val.programmaticStreamSerializationAllowed = 1;

    cudaLaunchConfig_t cfg = {};
    cfg.attrs = attr;
    cfg.numAttrs = 1;
    cfg.stream = 0;

    cfg.gridDim = dim3(NN); cfg.blockDim = dim3(256);
    cudaLaunchKernelEx(&cfg, ga_kernel, b);

    cfg.gridDim = dim3(1); cfg.blockDim = dim3(256);
    cudaLaunchKernelEx(&cfg, scan_kernel);

    cfg.gridDim = dim3(NB); cfg.blockDim = dim3(512);
    cudaLaunchKernelEx(&cfg, traj_kernel, (float*)d_out);
}

// round 13
// speedup vs baseline: 1.4041x; 1.3465x over previous
#include <cuda_runtime.h>
#include <math.h>

#define NB 512   // batch
#define NF 512   // features
#define NS 255   // splits
#define NN 511   // nodes
#define NC 21    // candidates

#define QSCALE 268435456.0                 // 2^28
#define QINV   3.7252902984619140625e-09f  // 2^-28

// ---------------- scratch (no allocations allowed) ----------------
__device__ unsigned long long g_qsplitI[NS * NB]; // [s][b] fixed-point accum
__device__ float g_qnodeT[NN * NB];               // [n][b]
__device__ float g_ga    [NN * NC];
__device__ float g_anode [NN];
__device__ volatile int g_scanDone;               // 0 at every launch start (self-resetting)

// PDL: wait until the preceding kernel's writes are visible
__device__ __forceinline__ void pdl_wait() {
    asm volatile("griddepcontrol.wait;" ::: "memory");
}

// ================= kernel 1: split-K GEMM, transposed output (FROZEN: R8) =================
__global__ __launch_bounds__(256, 2)
void gemm_kernel(const float* __restrict__ x, const float* __restrict__ W)
{
    __shared__ float As[64][68];   // [f][s]
    __shared__ float Bs[64][68];   // [f][b]

    int tid   = threadIdx.x;
    int k0    = blockIdx.x * 64;
    int bBase = blockIdx.y * 64;
    int sBase = blockIdx.z * 64;

    {
        int s = tid & 63, f0 = tid >> 6;
        int gs = sBase + s;
#pragma unroll
        for (int i = 0; i < 16; i++) {
            int f = f0 + i * 4;
            As[f][s] = (gs < NS) ? W[(k0 + f) * NS + gs] : 0.0f;
        }
        int fb = tid & 63, b0 = tid >> 6;
#pragma unroll
        for (int i = 0; i < 16; i++) {
            int b = b0 + i * 4;
            Bs[fb][b] = x[(bBase + b) * NF + k0 + fb];
        }
    }
    __syncthreads();

    int tr = tid >> 4;   // s quad
    int tc = tid & 15;   // b quad
    float acc[4][4];
#pragma unroll
    for (int i = 0; i < 4; i++)
#pragma unroll
        for (int j = 0; j < 4; j++) acc[i][j] = 0.0f;

#pragma unroll
    for (int f = 0; f < 64; f++) {
        float4 a4 = *(const float4*)&As[f][tr * 4];
        float4 b4 = *(const float4*)&Bs[f][tc * 4];
        float av[4] = {a4.x, a4.y, a4.z, a4.w};
        float bv[4] = {b4.x, b4.y, b4.z, b4.w};
#pragma unroll
        for (int i = 0; i < 4; i++)
#pragma unroll
            for (int j = 0; j < 4; j++) acc[i][j] += av[i] * bv[j];
    }

#pragma unroll
    for (int i = 0; i < 4; i++) {
        int s = sBase + tr * 4 + i;
        if (s < NS) {
#pragma unroll
            for (int j = 0; j < 4; j++) {
                int b = bBase + tc * 4 + j;
                long long q = __double2ll_rn((double)acc[i][j] * QSCALE);
                atomicAdd(&g_qsplitI[s * NB + b], (unsigned long long)q);
            }
        }
    }
}

// ================= kernel 2: q_node (ancestor walk) + g_a reduction (FROZEN: R8) =================
__global__ __launch_bounds__(256)
void ga_kernel(const float* __restrict__ bias)
{
    pdl_wait();   // g_qsplitI must be complete

    int n   = blockIdx.x;
    int tid = threadIdx.x;

    float accs[NC];
#pragma unroll
    for (int c = 0; c < NC; c++) accs[c] = 0.0f;

#pragma unroll
    for (int rep = 0; rep < 2; rep++) {
        int b = tid + rep * 256;
        float m = 1.0f;
        int a = n;
        while (a > 0) {
            int p = (a - 1) >> 1;
            float q = (float)(long long)g_qsplitI[p * NB + b] * QINV + bias[p];
            m = fminf(m, (a == 2 * p + 1) ? -q : q);
            a = p;
        }
        g_qnodeT[n * NB + b] = m;
        float qh = m + 0.5f;
#pragma unroll
        for (int c = 0; c < NC; c++) {
            float d = fminf((float)c * (1.0f / 20.0f) - qh, 0.0f);
            accs[c] = fmaf(d, d, accs[c]);
        }
    }

#pragma unroll
    for (int c = 0; c < NC; c++)
#pragma unroll
        for (int o = 16; o > 0; o >>= 1)
            accs[c] += __shfl_down_sync(0xffffffffu, accs[c], o);

    __shared__ float sW[8][NC];
    int w = tid >> 5, l = tid & 31;
    if (l == 0) {
#pragma unroll
        for (int c = 0; c < NC; c++) sW[w][c] = accs[c];
    }
    __syncthreads();
    if (tid < NC) {
        float s = 0.0f;
#pragma unroll
        for (int ww = 0; ww < 8; ww++) s += sW[ww][tid];
        float ac = (float)tid * (1.0f / 20.0f);
        g_ga[n * NC + tid] = 0.5f * ac * ac + 0.5f * s;
    }
}

// ================= kernel 3: scan (block 0) + trajectory (blocks 1..256) =================
__device__ __forceinline__ float softmin_serial(int g, const float* sGa, const int* sK)
{
    float kg = (float)sK[g];
    int c1 = 2 * g + 1, c2 = 2 * g + 2;
    float k1 = (c1 < NN) ? (float)sK[c1] : 0.0f;
    float k2 = (c2 < NN) ? (float)sK[c2] : 0.0f;
    const float* r0 = &sGa[g * NC];
    const float* r1 = (c1 < NN) ? &sGa[c1 * NC] : r0;
    const float* r2 = (c2 < NN) ? &sGa[c2 * NC] : r0;

    float v[NC];
    float m = -3.0e38f;
#pragma unroll
    for (int c = 0; c < NC; c++) {
        float t = (1.0f - kg) * r0[c] + k1 * r1[c] + k2 * r2[c];
        v[c] = -100.0f * t;
        m = fmaxf(m, v[c]);
    }
    float su = 0.0f, asu = 0.0f;
#pragma unroll
    for (int c = 0; c < NC; c++) {
        float e = __expf(v[c] - m);
        su += e;
        asu += (float)c * (1.0f / 20.0f) * e;
    }
    return asu / su;
}

// order-preserving float -> u32 (exact)
__device__ __forceinline__ unsigned fenc(float f)
{
    unsigned b = __float_as_uint(f);
    return (b & 0x80000000u) ? ~b : (b | 0x80000000u);
}

__global__ __launch_bounds__(256)
void scan_traj_kernel(float* __restrict__ out)
{
    __shared__ float sGa[NN * NC];   // 42924 B (waiters reuse the front as the transpose tile)
    __shared__ float sAgrp[NN];
    __shared__ float sAnode[NN];
    __shared__ int   sK[NN];         // 49056 B total (<= 48KB static cap)

    pdl_wait();   // g_ga / g_qnodeT must be complete

    int tid = threadIdx.x;

    if (blockIdx.x != 0) {
        // ---------- waiter blocks 1..256: re-zero accumulator, wait, transpose ----------
        // independent work first (hides the wait): re-zero g_qsplitI
        {
            ulonglong2 z; z.x = 0ULL; z.y = 0ULL;
            ulonglong2* p = (ulonglong2*)g_qsplitI;
            for (int i = (int)(blockIdx.x - 1) * 256 + tid; i < NS * NB / 2; i += 256 * 256)
                p[i] = z;
        }
        // wait for block 0 to publish g_anode
        if (tid == 0) {
            while (g_scanDone == 0) { }
            __threadfence();         // acquire
        }
        __syncthreads();

        // R8 traj body: 32x32 transpose tile, coalesced both sides
        float (*tile)[33] = (float (*)[33])sGa;
        int bid = (int)blockIdx.x - 1;
        int tn = bid >> 4, tb = bid & 15;
        int n0 = tn * 32, b0 = tb * 32;

#pragma unroll
        for (int pass = 0; pass < 4; pass++) {
            int r = (tid >> 5) + pass * 8, c = tid & 31;
            int n = n0 + r;
            float v = 0.0f;
            if (n < NN) {
                float q = g_qnodeT[n * NB + b0 + c];          // coalesced over b
                v = fminf(fmaxf(q, 0.0f), g_anode[n]);
            }
            tile[r][c] = v;
        }
        __syncthreads();
#pragma unroll
        for (int pass = 0; pass < 4; pass++) {
            int r = (tid >> 5) + pass * 8, c = tid & 31;
            int n = n0 + c;
            if (n < NN) out[(b0 + r) * NN + n] = tile[c][r];  // coalesced over n
        }

        // self-reset: 256 waiters each subtract 1 -> flag returns to 0 before next replay
        __syncthreads();
        if (tid == 0) atomicSub((int*)&g_scanDone, 1);
        return;
    }

    // ---------- block 0: the scan (FROZEN: R8 body) ----------
    for (int i = tid; i < NN * NC; i += 256) sGa[i] = g_ga[i];
    for (int i = tid; i < NN; i += 256) sK[i] = 0;
    __syncthreads();

    // initial a_grp (k==0 -> own-row softmin); a_node == a_grp initially
    for (int i = tid; i < NN; i += 256) {
        const float* r = &sGa[i * NC];
        float m = -3.0e38f;
#pragma unroll
        for (int c = 0; c < NC; c++) m = fmaxf(m, -100.0f * r[c]);
        float su = 0.0f, asu = 0.0f;
#pragma unroll
        for (int c = 0; c < NC; c++) {
            float e = __expf(-100.0f * r[c] - m);
            su += e; asu += (float)c * (1.0f / 20.0f) * e;
        }
        float ag = asu / su;
        sAgrp[i]  = ag;
        sAnode[i] = ag;
    }
    __syncthreads();

    if (tid < 32) {
        int lane = tid;
        int applied = 0;
        const unsigned THRESH = fenc(1e-8f);
        for (;;) {
            // per-lane best over 16 interleaved nodes (conflict-free LDS, first-index ties)
            float bv = -3.0e38f; int bi = NN;
#pragma unroll
            for (int i = 0; i < 16; i++) {
                int n = i * 32 + lane;
                if (n < NN) {
                    float an = sAnode[n];
                    float ap = (n == 0) ? 1.0f : sAnode[(n - 1) >> 1];
                    float v = an - ap;
                    if (v > bv || (v == bv && n < bi)) { bv = v; bi = n; }
                }
            }
            // exact warp argmax via REDUX: max on encoded value, min index among max-lanes
            unsigned enc  = fenc(bv);
            unsigned vmax = __reduce_max_sync(0xffffffffu, enc);
            unsigned cand = (enc == vmax) ? (unsigned)bi : 0xffffffffu;
            unsigned gbi  = __reduce_min_sync(0xffffffffu, cand);
            int t = (vmax <= THRESH && gbi > 0u) ? (int)gbi : -1;

            if (t < 0 || applied >= NN) break;   // fixed point / 512th body's merge discarded
            applied++;
            if (lane == 0) sK[t] += 1;
            __syncwarp();

            int p = (t - 1) >> 1;
            float na = 0.0f;
            if (lane < 2) na = softmin_serial(lane == 0 ? p : t, sGa, sK);
            if (lane == 0) sAgrp[p] = na;
            else if (lane == 1) sAgrp[t] = na;
            __syncwarp();

            // incremental a_node refresh: exactly {p, t, sib(t), 2t+1, 2t+2}
            if (lane < 5) {
                int s0 = 2 * p + 1, s1 = 2 * p + 2;
                int sib = (s0 == t) ? s1 : s0;
                int m = (lane == 0) ? p : (lane == 1) ? t : (lane == 2) ? sib
                      : (lane == 3) ? 2 * t + 1 : 2 * t + 2;
                if (m < NN) {
                    float an;
                    if (m == 0) an = sAgrp[0];
                    else {
                        float k = (float)sK[m];
                        an = (1.0f - k) * sAgrp[m] + k * sAgrp[(m - 1) >> 1];
                    }
                    sAnode[m] = an;
                }
            }
            __syncwarp();
        }
    }
    __syncthreads();

    for (int i = tid; i < NN; i += 256) g_anode[i] = sAnode[i];

    // publish: release-fence by every thread, then set the flag (add 256; waiters sub it back)
    __threadfence();
    __syncthreads();
    if (tid == 0) atomicAdd((int*)&g_scanDone, 256);
}

// ---------------- launch (3 kernels; PDL on the dependent ones) ----------------
extern "C" void kernel_launch(void* const* d_in, const int* in_sizes, int n_in,
                              void* d_out, int out_size)
{
    const float* x = (const float*)d_in[0];
    const float* W = (const float*)d_in[1];
    const float* b = (const float*)d_in[2];
    // d_in[3] = max_depth (fixed at 8; shapes hardcoded)

    gemm_kernel<<<dim3(8, 8, 4), 256>>>(x, W);

    cudaLaunchAttribute attr[1];
    attr[0].id = cudaLaunchAttributeProgrammaticStreamSerialization;
    attr[0].val.programmaticStreamSerializationAllowed = 1;

    cudaLaunchConfig_t cfg = {};
    cfg.attrs = attr;
    cfg.numAttrs = 1;
    cfg.stream = 0;

    cfg.gridDim = dim3(NN); cfg.blockDim = dim3(256);
    cudaLaunchKernelEx(&cfg, ga_kernel, b);

    cfg.gridDim = dim3(257); cfg.blockDim = dim3(256);   // block 0 scan, 1..256 traj
    cudaLaunchKernelEx(&cfg, scan_traj_kernel, (float*)d_out);
}

// round 16
// speedup vs baseline: 1.7105x; 1.2182x over previous
#include <cuda_runtime.h>
#include <math.h>

#define NB 512   // batch
#define NF 512   // features
#define NS 255   // splits
#define NN 511   // nodes
#define NC 21    // candidates

#define QSCALEF 268435456.0f               // 2^28 (exact exponent shift in fp32)
#define QINV   3.7252902984619140625e-09f  // 2^-28

// ---------------- scratch (no allocations allowed) ----------------
__device__ unsigned long long g_qsplitI[NS * NB]; // [s][b] fixed-point accum (re-zeroed by traj_kernel)
__device__ float g_qnodeT[NN * NB];               // [n][b]
__device__ float g_ga    [NN * NC];
__device__ float g_anode [NN];

// PDL: wait until the preceding kernel's writes are visible
__device__ __forceinline__ void pdl_wait() {
    asm volatile("griddepcontrol.wait;" ::: "memory");
}

// ================= kernel 1: split-K GEMM — occupancy-fixed =================
// qsplitT[s][b] = sum_f W[f][s] * x[b][f]; grid (ksplit=8, bTile=8, sTile=4), 256 thr.
// R13 profile: full 64-unroll -> 128 regs -> 2 blocks/SM -> occ 24.6%, 19.3 us.
// Fix: unroll 8 + reg cap 85 (launch_bounds 256,3) -> 3 blocks/SM, 24 warps.
// Epilogue: float path for fixed-point convert (bit-identical: *2^28 is exact in fp32).
__global__ __launch_bounds__(256, 3)
void gemm_kernel(const float* __restrict__ x, const float* __restrict__ W)
{
    __shared__ float As[64][68];   // [f][s]
    __shared__ float Bs[64][68];   // [f][b]

    int tid   = threadIdx.x;
    int k0    = blockIdx.x * 64;
    int bBase = blockIdx.y * 64;
    int sBase = blockIdx.z * 64;

    {
        int s = tid & 63, f0 = tid >> 6;
        int gs = sBase + s;
#pragma unroll
        for (int i = 0; i < 16; i++) {
            int f = f0 + i * 4;
            As[f][s] = (gs < NS) ? W[(k0 + f) * NS + gs] : 0.0f;
        }
        int fb = tid & 63, b0 = tid >> 6;
#pragma unroll
        for (int i = 0; i < 16; i++) {
            int b = b0 + i * 4;
            Bs[fb][b] = x[(bBase + b) * NF + k0 + fb];
        }
    }
    __syncthreads();

    int tr = tid >> 4;   // s quad
    int tc = tid & 15;   // b quad
    float acc[4][4];
#pragma unroll
    for (int i = 0; i < 4; i++)
#pragma unroll
        for (int j = 0; j < 4; j++) acc[i][j] = 0.0f;

#pragma unroll 8
    for (int f = 0; f < 64; f++) {
        float4 a4 = *(const float4*)&As[f][tr * 4];
        float4 b4 = *(const float4*)&Bs[f][tc * 4];
        float av[4] = {a4.x, a4.y, a4.z, a4.w};
        float bv[4] = {b4.x, b4.y, b4.z, b4.w};
#pragma unroll
        for (int i = 0; i < 4; i++)
#pragma unroll
            for (int j = 0; j < 4; j++) acc[i][j] += av[i] * bv[j];
    }

#pragma unroll
    for (int i = 0; i < 4; i++) {
        int s = sBase + tr * 4 + i;
        if (s < NS) {
#pragma unroll
            for (int j = 0; j < 4; j++) {
                int b = bBase + tc * 4 + j;
                long long q = __float2ll_rn(acc[i][j] * QSCALEF);   // exact: *2^28 shifts exponent only
                atomicAdd(&g_qsplitI[s * NB + b], (unsigned long long)q);
            }
        }
    }
}

// ================= kernel 2: q_node (ancestor walk) + g_a reduction (FROZEN: R8) =================
__global__ __launch_bounds__(256)
void ga_kernel(const float* __restrict__ bias)
{
    pdl_wait();   // g_qsplitI must be complete

    int n   = blockIdx.x;
    int tid = threadIdx.x;

    float accs[NC];
#pragma unroll
    for (int c = 0; c < NC; c++) accs[c] = 0.0f;

#pragma unroll
    for (int rep = 0; rep < 2; rep++) {
        int b = tid + rep * 256;
        float m = 1.0f;
        int a = n;
        while (a > 0) {
            int p = (a - 1) >> 1;
            float q = (float)(long long)g_qsplitI[p * NB + b] * QINV + bias[p];
            m = fminf(m, (a == 2 * p + 1) ? -q : q);
            a = p;
        }
        g_qnodeT[n * NB + b] = m;
        float qh = m + 0.5f;
#pragma unroll
        for (int c = 0; c < NC; c++) {
            float d = fminf((float)c * (1.0f / 20.0f) - qh, 0.0f);
            accs[c] = fmaf(d, d, accs[c]);
        }
    }

#pragma unroll
    for (int c = 0; c < NC; c++)
#pragma unroll
        for (int o = 16; o > 0; o >>= 1)
            accs[c] += __shfl_down_sync(0xffffffffu, accs[c], o);

    __shared__ float sW[8][NC];
    int w = tid >> 5, l = tid & 31;
    if (l == 0) {
#pragma unroll
        for (int c = 0; c < NC; c++) sW[w][c] = accs[c];
    }
    __syncthreads();
    if (tid < NC) {
        float s = 0.0f;
#pragma unroll
        for (int ww = 0; ww < 8; ww++) s += sW[ww][tid];
        float ac = (float)tid * (1.0f / 20.0f);
        g_ga[n * NC + tid] = 0.5f * ac * ac + 0.5f * s;
    }
}

// ================= kernel 3: the scan (FROZEN: R8) =================
__device__ __forceinline__ float softmin_serial(int g, const float* sGa, const int* sK)
{
    float kg = (float)sK[g];
    int c1 = 2 * g + 1, c2 = 2 * g + 2;
    float k1 = (c1 < NN) ? (float)sK[c1] : 0.0f;
    float k2 = (c2 < NN) ? (float)sK[c2] : 0.0f;
    const float* r0 = &sGa[g * NC];
    const float* r1 = (c1 < NN) ? &sGa[c1 * NC] : r0;
    const float* r2 = (c2 < NN) ? &sGa[c2 * NC] : r0;

    float v[NC];
    float m = -3.0e38f;
#pragma unroll
    for (int c = 0; c < NC; c++) {
        float t = (1.0f - kg) * r0[c] + k1 * r1[c] + k2 * r2[c];
        v[c] = -100.0f * t;
        m = fmaxf(m, v[c]);
    }
    float su = 0.0f, asu = 0.0f;
#pragma unroll
    for (int c = 0; c < NC; c++) {
        float e = __expf(v[c] - m);
        su += e;
        asu += (float)c * (1.0f / 20.0f) * e;
    }
    return asu / su;
}

// order-preserving float -> u32 (exact)
__device__ __forceinline__ unsigned fenc(float f)
{
    unsigned b = __float_as_uint(f);
    return (b & 0x80000000u) ? ~b : (b | 0x80000000u);
}

__global__ __launch_bounds__(256)
void scan_kernel()
{
    __shared__ float sGa[NN * NC];   // 42924 B
    __shared__ float sAgrp[NN];
    __shared__ float sAnode[NN];
    __shared__ int   sK[NN];

    pdl_wait();   // g_ga must be complete

    int tid = threadIdx.x;

    for (int i = tid; i < NN * NC; i += 256) sGa[i] = g_ga[i];
    for (int i = tid; i < NN; i += 256) sK[i] = 0;
    __syncthreads();

    // initial a_grp (k==0 -> own-row softmin); a_node == a_grp initially
    for (int i = tid; i < NN; i += 256) {
        const float* r = &sGa[i * NC];
        float m = -3.0e38f;
#pragma unroll
        for (int c = 0; c < NC; c++) m = fmaxf(m, -100.0f * r[c]);
        float su = 0.0f, asu = 0.0f;
#pragma unroll
        for (int c = 0; c < NC; c++) {
            float e = __expf(-100.0f * r[c] - m);
            su += e; asu += (float)c * (1.0f / 20.0f) * e;
        }
        float ag = asu / su;
        sAgrp[i]  = ag;
        sAnode[i] = ag;
    }
    __syncthreads();

    if (tid < 32) {
        int lane = tid;
        int applied = 0;
        const unsigned THRESH = fenc(1e-8f);
        for (;;) {
            // per-lane best over 16 interleaved nodes (conflict-free LDS, first-index ties)
            float bv = -3.0e38f; int bi = NN;
#pragma unroll
            for (int i = 0; i < 16; i++) {
                int n = i * 32 + lane;
                if (n < NN) {
                    float an = sAnode[n];
                    float ap = (n == 0) ? 1.0f : sAnode[(n - 1) >> 1];
                    float v = an - ap;
                    if (v > bv || (v == bv && n < bi)) { bv = v; bi = n; }
                }
            }
            // exact warp argmax via REDUX: max on encoded value, min index among max-lanes
            unsigned enc  = fenc(bv);
            unsigned vmax = __reduce_max_sync(0xffffffffu, enc);
            unsigned cand = (enc == vmax) ? (unsigned)bi : 0xffffffffu;
            unsigned gbi  = __reduce_min_sync(0xffffffffu, cand);
            int t = (vmax <= THRESH && gbi > 0u) ? (int)gbi : -1;

            if (t < 0 || applied >= NN) break;   // fixed point / 512th body's merge discarded
            applied++;
            if (lane == 0) sK[t] += 1;
            __syncwarp();

            int p = (t - 1) >> 1;
            float na = 0.0f;
            if (lane < 2) na = softmin_serial(lane == 0 ? p : t, sGa, sK);
            if (lane == 0) sAgrp[p] = na;
            else if (lane == 1) sAgrp[t] = na;
            __syncwarp();

            // incremental a_node refresh: exactly {p, t, sib(t), 2t+1, 2t+2}
            if (lane < 5) {
                int s0 = 2 * p + 1, s1 = 2 * p + 2;
                int sib = (s0 == t) ? s1 : s0;
                int m = (lane == 0) ? p : (lane == 1) ? t : (lane == 2) ? sib
                      : (lane == 3) ? 2 * t + 1 : 2 * t + 2;
                if (m < NN) {
                    float an;
                    if (m == 0) an = sAgrp[0];
                    else {
                        float k = (float)sK[m];
                        an = (1.0f - k) * sAgrp[m] + k * sAgrp[(m - 1) >> 1];
                    }
                    sAnode[m] = an;
                }
            }
            __syncwarp();
        }
    }
    __syncthreads();

    for (int i = tid; i < NN; i += 256) g_anode[i] = sAnode[i];
}

// ================= kernel 4: transposed trajectory + distributed re-zero (FROZEN: R8) ====
__global__ __launch_bounds__(256)
void traj_kernel(float* __restrict__ out)
{
    __shared__ float tile[32][33];

    pdl_wait();   // g_anode / g_qnodeT must be complete

    int tid = threadIdx.x;
    int tn = blockIdx.x >> 4, tb = blockIdx.x & 15;
    int n0 = tn * 32, b0 = tb * 32;

#pragma unroll
    for (int pass = 0; pass < 4; pass++) {
        int r = (tid >> 5) + pass * 8, c = tid & 31;
        int n = n0 + r;
        float v = 0.0f;
        if (n < NN) {
            float q = g_qnodeT[n * NB + b0 + c];          // coalesced over b
            v = fminf(fmaxf(q, 0.0f), g_anode[n]);
        }
        tile[r][c] = v;
    }
    __syncthreads();
#pragma unroll
    for (int pass = 0; pass < 4; pass++) {
        int r = (tid >> 5) + pass * 8, c = tid & 31;
        int n = n0 + c;
        if (n < NN) out[(b0 + r) * NN + n] = tile[c][r];  // coalesced over n
    }

    // re-zero fixed-point accumulator for next launch, spread over 256 blocks
    ulonglong2 z; z.x = 0ULL; z.y = 0ULL;
    ulonglong2* p = (ulonglong2*)g_qsplitI;
    for (int i = blockIdx.x * 256 + tid; i < NS * NB / 2; i += 256 * 256) p[i] = z;
}

// ---------------- launch (PDL on the three dependent kernels) ----------------
extern "C" void kernel_launch(void* const* d_in, const int* in_sizes, int n_in,
                              void* d_out, int out_size)
{
    const float* x = (const float*)d_in[0];
    const float* W = (const float*)d_in[1];
    const float* b = (const float*)d_in[2];
    // d_in[3] = max_depth (fixed at 8; shapes hardcoded)

    gemm_kernel<<<dim3(8, 8, 4), 256>>>(x, W);

    cudaLaunchAttribute attr[1];
    attr[0].id = cudaLaunchAttributeProgrammaticStreamSerialization;
    attr[0].val.programmaticStreamSerializationAllowed = 1;

    cudaLaunchConfig_t cfg = {};
    cfg.attrs = attr;
    cfg.numAttrs = 1;
    cfg.stream = 0;

    cfg.gridDim = dim3(NN); cfg.blockDim = dim3(256);
    cudaLaunchKernelEx(&cfg, ga_kernel, b);

    cfg.gridDim = dim3(1); cfg.blockDim = dim3(256);
    cudaLaunchKernelEx(&cfg, scan_kernel);

    cfg.gridDim = dim3(256); cfg.blockDim = dim3(256);
    cudaLaunchKernelEx(&cfg, traj_kernel, (float*)d_out);
}